// round 3
// baseline (speedup 1.0000x reference)
#include <cuda_runtime.h>
#include <cstdint>

// Weighted cross-entropy (sum reduction):
//   loss = sum_r  w[t_r] * ( logsumexp(logits[r,:]) - logits[r, t_r] )
//
// Single-pass online softmax, chunked so the (m,s) merge costs 2 EX2 per
// 8-element chunk (~1.25 EX2/element) -> MUFU stays under the DRAM roofline.
// Deterministic: per-row losses -> __device__ scratch -> fixed-order reduce.
//
// NOTE: targets are int32 (JAX default x64-disabled downcasts int64 -> int32).

#define TPB 256
#define UNROLL 8
#define NEG_BIG (-1e30f)
#define L2E 1.4426950408889634f   // log2(e)
#define LN2 0.6931471805599453f   // ln(2)

__device__ float g_row_loss[65536];  // scratch (N=8192; sized generously)

__device__ __forceinline__ float ex2f(float x) {
    float y;
    asm("ex2.approx.ftz.f32 %0, %1;" : "=f"(y) : "f"(x));
    return y;
}
__device__ __forceinline__ float lg2f(float x) {
    float y;
    asm("lg2.approx.ftz.f32 %0, %1;" : "=f"(y) : "f"(x));
    return y;
}

__global__ __launch_bounds__(TPB)
void ce_row_kernel(const float* __restrict__ logits,
                   const int* __restrict__ target,
                   const float* __restrict__ weights,
                   int C) {
    const int row = blockIdx.x;
    const float* __restrict__ rp = logits + (size_t)row * (size_t)C;

    // Online (m, s): s = sum_i exp(x_i - m), m = running max.
    float m = NEG_BIG;
    float s = 0.0f;

    const int stride = TPB * UNROLL;
    for (int base = 0; base < C; base += stride) {
        float v[UNROLL];
#pragma unroll
        for (int u = 0; u < UNROLL; u++) {
            int idx = base + (int)threadIdx.x + u * TPB;
            v[u] = (idx < C) ? __ldg(rp + idx) : NEG_BIG;
        }
        // chunk max (ALU pipe, cheap)
        float mc = v[0];
#pragma unroll
        for (int u = 1; u < UNROLL; u++) mc = fmaxf(mc, v[u]);

        // sum of exp relative to chunk max: one MUFU per element
        float b = mc * L2E;
        float sc = 0.0f;
#pragma unroll
        for (int u = 0; u < UNROLL; u++)
            sc += ex2f(__fmaf_rn(v[u], L2E, -b));

        // merge chunk into running (m, s): 2 EX2 per chunk
        float M = fmaxf(m, mc);
        s = s * ex2f((m - M) * L2E) + sc * ex2f((mc - M) * L2E);
        m = M;
    }

    // warp-level (m, s) combine
#pragma unroll
    for (int off = 16; off; off >>= 1) {
        float mo = __shfl_xor_sync(0xffffffffu, m, off);
        float so = __shfl_xor_sync(0xffffffffu, s, off);
        float M = fmaxf(m, mo);
        s = s * ex2f((m - M) * L2E) + so * ex2f((mo - M) * L2E);
        m = M;
    }

    __shared__ float sh_m[TPB / 32];
    __shared__ float sh_s[TPB / 32];
    const int wid = threadIdx.x >> 5;
    const int lid = threadIdx.x & 31;
    if (lid == 0) { sh_m[wid] = m; sh_s[wid] = s; }
    __syncthreads();

    if (threadIdx.x == 0) {
        float M = sh_m[0], S = sh_s[0];
#pragma unroll
        for (int i = 1; i < TPB / 32; i++) {
            float mo = sh_m[i], so = sh_s[i];
            float Mn = fmaxf(M, mo);
            S = S * ex2f((M - Mn) * L2E) + so * ex2f((mo - Mn) * L2E);
            M = Mn;
        }
        int t = target[row];
        // clamp defensively (garbage target must not fault; wrong value would
        // surface as rel_err instead, which is debuggable)
        if (t < 0) t = 0;
        if (t >= C) t = C - 1;
        float xt = __ldg(rp + (size_t)t);
        float lse = M + lg2f(S) * LN2;
        g_row_loss[row] = weights[t] * (lse - xt);
    }
}

// Deterministic fixed-order reduction of per-row losses -> scalar.
__global__ __launch_bounds__(TPB)
void ce_reduce_kernel(float* __restrict__ out, int N) {
    float acc = 0.0f;
    for (int i = threadIdx.x; i < N; i += TPB)
        acc += g_row_loss[i];

    __shared__ float sh[TPB];
    sh[threadIdx.x] = acc;
    __syncthreads();
#pragma unroll
    for (int step = TPB / 2; step > 0; step >>= 1) {
        if (threadIdx.x < step) sh[threadIdx.x] += sh[threadIdx.x + step];
        __syncthreads();
    }
    if (threadIdx.x == 0) out[0] = sh[0];
}

extern "C" void kernel_launch(void* const* d_in, const int* in_sizes, int n_in,
                              void* d_out, int out_size) {
    const float* logits  = (const float*)d_in[0];
    const int*   target  = (const int*)d_in[1];
    const float* weights = (const float*)d_in[2];

    const int N = in_sizes[1];   // number of rows (targets)
    const int C = in_sizes[2];   // number of classes (weights length)

    ce_row_kernel<<<N, TPB>>>(logits, target, weights, C);
    ce_reduce_kernel<<<1, TPB>>>((float*)d_out, N);
}

// round 4
// speedup vs baseline: 1.0934x; 1.0934x over previous
#include <cuda_runtime.h>
#include <cstdint>

// Weighted cross-entropy (sum reduction), single pass, vectorized:
//   loss = sum_r  w[t_r] * ( logsumexp(logits[r,:]) - logits[r, t_r] )
//
// - LDG.128 body (float4), per-row alignment peel (C % 4 == 1 rotates base).
// - Chunked online softmax: 16 floats/chunk -> 1.125 EX2/element.
// - Fused deterministic final reduce: last CTA (atomic counter) sums the
//   per-row losses in fixed order. Counter self-resets for graph replay.

#define TPB 256
#define VUNROLL 4                  // float4 per thread per iteration
#define NEG_BIG (-1e30f)
#define L2E 1.4426950408889634f    // log2(e)
#define LN2 0.6931471805599453f    // ln(2)

__device__ float g_row_loss[65536];
__device__ unsigned g_ctr = 0;

__device__ __forceinline__ float ex2f(float x) {
    float y;
    asm("ex2.approx.ftz.f32 %0, %1;" : "=f"(y) : "f"(x));
    return y;
}
__device__ __forceinline__ float lg2f(float x) {
    float y;
    asm("lg2.approx.ftz.f32 %0, %1;" : "=f"(y) : "f"(x));
    return y;
}

// Merge one value chunk (mc, sc) into running (m, s).
__device__ __forceinline__ void merge_ms(float& m, float& s, float mc, float sc) {
    float M = fmaxf(m, mc);
    s = s * ex2f((m - M) * L2E) + sc * ex2f((mc - M) * L2E);
    m = M;
}

__global__ __launch_bounds__(TPB)
void ce_row_kernel(const float* __restrict__ logits,
                   const int* __restrict__ target,
                   const float* __restrict__ weights,
                   float* __restrict__ out,
                   int C, int N) {
    const int row = blockIdx.x;
    const float* __restrict__ rp = logits + (size_t)row * (size_t)C;

    // Alignment peel: rp is 16B-aligned iff (row*C) % 4 == 0.
    const int off = (int)(((size_t)row * (size_t)C) & 3);
    const int pre = (4 - off) & 3;              // scalar elements before body
    const int nvec = (C - pre) >> 2;            // aligned float4 count
    const int rem = (C - pre) & 3;              // scalar tail elements
    const float4* __restrict__ vp = (const float4*)(rp + pre);

    float m = NEG_BIG;
    float s = 0.0f;

    // --- scalar peel (<=3 elems): singleton chunks on threads 0..pre-1 ---
    if ((int)threadIdx.x < pre)
        merge_ms(m, s, __ldg(rp + threadIdx.x), 1.0f);
    // --- scalar tail (<=3 elems): threads 0..rem-1 ---
    if ((int)threadIdx.x < rem)
        merge_ms(m, s, __ldg(rp + pre + nvec * 4 + threadIdx.x), 1.0f);

    // --- vector body: full iterations without bounds checks ---
    const int stride = TPB * VUNROLL;
    const int nfull = nvec / stride;
    int base = 0;
    for (int it = 0; it < nfull; it++, base += stride) {
        float4 v[VUNROLL];
#pragma unroll
        for (int u = 0; u < VUNROLL; u++)
            v[u] = __ldg(vp + base + (int)threadIdx.x + u * TPB);

        float mc = fmaxf(fmaxf(v[0].x, v[0].y), fmaxf(v[0].z, v[0].w));
#pragma unroll
        for (int u = 1; u < VUNROLL; u++)
            mc = fmaxf(mc, fmaxf(fmaxf(v[u].x, v[u].y), fmaxf(v[u].z, v[u].w)));

        float b = mc * L2E;
        float sc = 0.0f;
#pragma unroll
        for (int u = 0; u < VUNROLL; u++) {
            sc += ex2f(__fmaf_rn(v[u].x, L2E, -b));
            sc += ex2f(__fmaf_rn(v[u].y, L2E, -b));
            sc += ex2f(__fmaf_rn(v[u].z, L2E, -b));
            sc += ex2f(__fmaf_rn(v[u].w, L2E, -b));
        }
        merge_ms(m, s, mc, sc);
    }

    // --- vector remainder: per-float4 predication ---
    {
        float4 v[VUNROLL];
        const float4 neg = make_float4(NEG_BIG, NEG_BIG, NEG_BIG, NEG_BIG);
#pragma unroll
        for (int u = 0; u < VUNROLL; u++) {
            int idx = base + (int)threadIdx.x + u * TPB;
            v[u] = (idx < nvec) ? __ldg(vp + idx) : neg;
        }
        float mc = fmaxf(fmaxf(v[0].x, v[0].y), fmaxf(v[0].z, v[0].w));
#pragma unroll
        for (int u = 1; u < VUNROLL; u++)
            mc = fmaxf(mc, fmaxf(fmaxf(v[u].x, v[u].y), fmaxf(v[u].z, v[u].w)));

        float b = mc * L2E;
        float sc = 0.0f;
#pragma unroll
        for (int u = 0; u < VUNROLL; u++) {
            sc += ex2f(__fmaf_rn(v[u].x, L2E, -b));
            sc += ex2f(__fmaf_rn(v[u].y, L2E, -b));
            sc += ex2f(__fmaf_rn(v[u].z, L2E, -b));
            sc += ex2f(__fmaf_rn(v[u].w, L2E, -b));
        }
        merge_ms(m, s, mc, sc);  // all-NEG_BIG chunk is harmless: sc scaled to 0
    }

    // --- warp combine ---
#pragma unroll
    for (int offx = 16; offx; offx >>= 1) {
        float mo = __shfl_xor_sync(0xffffffffu, m, offx);
        float so = __shfl_xor_sync(0xffffffffu, s, offx);
        merge_ms(m, s, mo, so);
    }

    __shared__ float sh_m[TPB / 32];
    __shared__ float sh_s[TPB / 32];
    const int wid = threadIdx.x >> 5;
    if ((threadIdx.x & 31) == 0) { sh_m[wid] = m; sh_s[wid] = s; }
    __syncthreads();

    if (threadIdx.x == 0) {
        float M = sh_m[0], S = sh_s[0];
#pragma unroll
        for (int i = 1; i < TPB / 32; i++)
            merge_ms(M, S, sh_m[i], sh_s[i]);

        int t = target[row];
        if (t < 0) t = 0;
        if (t >= C) t = C - 1;
        float xt = __ldg(rp + (size_t)t);
        float lse = M + lg2f(S) * LN2;
        g_row_loss[row] = weights[t] * (lse - xt);
    }

    // --- fused deterministic final reduce: last CTA sums all rows ---
    __shared__ int s_last;
    if (threadIdx.x == 0) {
        __threadfence();
        unsigned o = atomicAdd(&g_ctr, 1u);
        s_last = (o == (unsigned)(gridDim.x - 1)) ? 1 : 0;
    }
    __syncthreads();

    if (s_last) {
        __threadfence();  // acquire: make all g_row_loss stores visible
        float acc = 0.0f;
        for (int i = threadIdx.x; i < N; i += TPB)
            acc += g_row_loss[i];

        __shared__ float sh[TPB];
        sh[threadIdx.x] = acc;
        __syncthreads();
#pragma unroll
        for (int step = TPB / 2; step > 0; step >>= 1) {
            if ((int)threadIdx.x < step) sh[threadIdx.x] += sh[threadIdx.x + step];
            __syncthreads();
        }
        if (threadIdx.x == 0) {
            out[0] = sh[0];
            g_ctr = 0;  // reset for next graph replay
        }
    }
}

extern "C" void kernel_launch(void* const* d_in, const int* in_sizes, int n_in,
                              void* d_out, int out_size) {
    const float* logits  = (const float*)d_in[0];
    const int*   target  = (const int*)d_in[1];
    const float* weights = (const float*)d_in[2];

    const int N = in_sizes[1];   // rows
    const int C = in_sizes[2];   // classes

    ce_row_kernel<<<N, TPB>>>(logits, target, weights, (float*)d_out, C, N);
}